// round 12
// baseline (speedup 1.0000x reference)
#include <cuda_runtime.h>
#include <cuda_fp16.h>
#include <math.h>

#define NN 100000
#define NE 1600000
#define DF 64
#define SCB 98                // scan blocks: ceil(NN/1024)
#define XTS 136               // padded smem row stride in halfs (X and W tiles)
#define NTILE 1563            // ceil(NN/64)

typedef unsigned long long ull;

// ---------------- device scratch (static: no allocation allowed) ----------------
__device__ __half g_UVf[NN * 128];  // node c: ininv[c]*{U, Vf}   (fp16, pre-scaled)
__device__ __half g_UVt[NN * 128];  // node r: outinv[r]*{U, Vt}  (fp16, pre-scaled)
__device__ __half g_Wcat[192 * 128];// fused weights: rows = out col, cols = [xr|xi]
__device__ float g_outinv[NN];
__device__ float g_ininv [NN];
__device__ int   g_degout[NN];
__device__ int   g_degin [NN];
__device__ int   g_rs_fwd[NN + 1];
__device__ int   g_rs_rev[NN + 1];
__device__ int   g_cur_fwd[NN];
__device__ int   g_cur_rev[NN];
__device__ int   g_csr_fwd[NE];
__device__ int   g_csr_rev[NE];
__device__ int   g_bsum_fwd[SCB];
__device__ int   g_bsum_rev[SCB];
__device__ float g_bias[128];       // [0:64) breal_eff, [64:128) bimag_eff

// ---------------- helpers ----------------
__device__ __forceinline__ unsigned smem_u32(const void* p) {
    unsigned a;
    asm("{ .reg .u64 t; cvta.to.shared.u64 t, %1; cvt.u32.u64 %0, t; }" : "=r"(a) : "l"(p));
    return a;
}

// ---------------- kernels ----------------
// (A1) zero degree counters
__global__ void k_zero() {
    int i = blockIdx.x * blockDim.x + threadIdx.x;
    if (i < NN) { g_degout[i] = 0; g_degin[i] = 0; }
}

// (B1) build fused fp16 weight matrix Wcat + biases
__global__ void k_weights(const float* __restrict__ Wr, const float* __restrict__ br,
                          const float* __restrict__ Wi, const float* __restrict__ bi) {
    int i = blockIdx.x * blockDim.x + threadIdx.x;
    if (i < 192 * 128) {
        int gc = i >> 7, d2 = i & 127;
        float val = 0.0f;
        if (gc < 64) {
            int o = gc;
            if (d2 < 64) {
                int u = o * 64 + d2;
                val = 0.5f * (Wr[u] + 0.5f * Wr[4096 + u] + 0.25f * Wr[8192 + u]);
            } else {
                int u = o * 64 + (d2 - 64);
                val = -0.5f * (Wi[u] + 0.5f * Wi[4096 + u] + 0.25f * Wi[8192 + u]);
            }
        } else if (gc < 128) {
            int j = gc - 64;
            if (d2 < 64) {
                int u = j * 64 + d2;
                val = Wi[u] + 0.5f * Wi[4096 + u] + 0.25f * Wi[8192 + u];
            } else {
                int u = j * 64 + (d2 - 64);
                val = 0.5f * (Wr[u] + 0.5f * Wr[4096 + u] + 0.25f * Wr[8192 + u]);
            }
        } else {
            int j = gc - 128;
            if (d2 >= 64) {
                int u = j * 64 + (d2 - 64);
                val = 0.5f * (Wr[u] + 0.5f * Wr[4096 + u] + 0.25f * Wr[8192 + u]);
            }
        }
        g_Wcat[i] = __float2half_rn(val);
    }
    if (i < DF) {
        float bre = br[i] + 0.5f * br[64 + i] + 0.25f * br[128 + i];
        float bie = bi[i] + 0.5f * bi[64 + i] + 0.25f * bi[128 + i];
        g_bias[i]      = bre - bie;
        g_bias[64 + i] = bre + bie;
    }
}

// (A2) degree counting
__global__ void k_deg(const int* __restrict__ ei) {
    int i = blockIdx.x * blockDim.x + threadIdx.x;
    if (i < NE) {
        atomicAdd(&g_degout[ei[i]], 1);
        atomicAdd(&g_degin [ei[NE + i]], 1);
    }
}

// (A3) per-block degree sums + deg^-0.25 normalizers (fused)
__global__ __launch_bounds__(1024) void k_bsum_inv() {
    __shared__ int sf[1024], sr[1024];
    int t = threadIdx.x;
    int i = blockIdx.x * 1024 + t;
    int dout = 0, din = 0;
    if (i < NN) {
        dout = g_degout[i];
        din  = g_degin[i];
        g_outinv[i] = (dout > 0) ? rsqrtf(sqrtf((float)dout)) : 0.0f;
        g_ininv [i] = (din  > 0) ? rsqrtf(sqrtf((float)din )) : 0.0f;
    }
    sf[t] = dout; sr[t] = din;
    __syncthreads();
    for (int off = 512; off > 0; off >>= 1) {
        if (t < off) { sf[t] += sf[t + off]; sr[t] += sr[t + off]; }
        __syncthreads();
    }
    if (t == 0) {
        g_bsum_fwd[blockIdx.x] = sf[0];
        g_bsum_rev[blockIdx.x] = sr[0];
    }
}

// (B2) HMMA transform with weight folding: outputs pre-scaled by ininv/outinv.
// grid (NTILE,2); depends on bsum_inv (inv arrays).
__global__ __launch_bounds__(256) void k_transform(const float* __restrict__ xr,
                                                   const float* __restrict__ xi) {
    __shared__ __align__(16) __half sX[64 * XTS];
    __shared__ __align__(16) __half sW[96 * XTS];

    int t    = threadIdx.x;
    int lane = t & 31;
    int w    = t >> 5;
    int tilebase = blockIdx.x * 64;
    int chunk    = blockIdx.y;            // 0 or 1

    #pragma unroll
    for (int it = 0; it < 8; it++) {
        int idx = t + it * 256;
        int nd = idx >> 5, k = idx & 31;
        int node = tilebase + nd;
        float4 v = make_float4(0.f, 0.f, 0.f, 0.f);
        if (node < NN)
            v = (k < 16) ? ((const float4*)xr)[(size_t)node * 16 + k]
                         : ((const float4*)xi)[(size_t)node * 16 + (k - 16)];
        __half2 h0 = __floats2half2_rn(v.x, v.y);
        __half2 h1 = __floats2half2_rn(v.z, v.w);
        *(uint2*)(sX + nd * XTS + k * 4) = make_uint2(*(unsigned*)&h0, *(unsigned*)&h1);
    }
    #pragma unroll
    for (int it = 0; it < 12; it++) {
        int idx = t + it * 256;
        int r = idx >> 5, c = idx & 31;
        uint2 v = ((const uint2*)g_Wcat)[((size_t)(96 * chunk + r) << 5) + c];
        *(uint2*)(sW + r * XTS + c * 4) = v;
    }
    __syncthreads();

    int ngrp = w & 3;
    int ns   = w >> 2;
    int nodebase = 16 * ngrp;
    int colbase  = 48 * ns;

    unsigned a_addr = smem_u32(sX) +
        (unsigned)(((nodebase + (lane & 15)) * XTS + ((lane >> 4) * 8)) * 2);
    unsigned b_addr = smem_u32(sW) +
        (unsigned)(((colbase + ((lane >> 4) & 1) * 8 + (lane & 7)) * XTS
                    + ((lane >> 3) & 1) * 8) * 2);

    float acc[6][4];
    #pragma unroll
    for (int nt = 0; nt < 6; nt++)
        #pragma unroll
        for (int q = 0; q < 4; q++) acc[nt][q] = 0.0f;

    #pragma unroll
    for (int kk = 0; kk < 8; kk++) {
        unsigned a0, a1, a2, a3;
        asm volatile("ldmatrix.sync.aligned.m8n8.x4.shared.b16 {%0,%1,%2,%3}, [%4];"
                     : "=r"(a0), "=r"(a1), "=r"(a2), "=r"(a3)
                     : "r"(a_addr + kk * 32));
        #pragma unroll
        for (int p = 0; p < 3; p++) {
            unsigned b0, b1, b2, b3;
            asm volatile("ldmatrix.sync.aligned.m8n8.x4.shared.b16 {%0,%1,%2,%3}, [%4];"
                         : "=r"(b0), "=r"(b1), "=r"(b2), "=r"(b3)
                         : "r"(b_addr + p * (16 * XTS * 2) + kk * 32));
            asm volatile("mma.sync.aligned.m16n8k16.row.col.f32.f16.f16.f32 "
                         "{%0,%1,%2,%3}, {%4,%5,%6,%7}, {%8,%9}, {%0,%1,%2,%3};"
                         : "+f"(acc[2*p][0]), "+f"(acc[2*p][1]),
                           "+f"(acc[2*p][2]), "+f"(acc[2*p][3])
                         : "r"(a0), "r"(a1), "r"(a2), "r"(a3), "r"(b0), "r"(b1));
            asm volatile("mma.sync.aligned.m16n8k16.row.col.f32.f16.f16.f32 "
                         "{%0,%1,%2,%3}, {%4,%5,%6,%7}, {%8,%9}, {%0,%1,%2,%3};"
                         : "+f"(acc[2*p+1][0]), "+f"(acc[2*p+1][1]),
                           "+f"(acc[2*p+1][2]), "+f"(acc[2*p+1][3])
                         : "r"(a0), "r"(a1), "r"(a2), "r"(a3), "r"(b2), "r"(b3));
        }
    }

    // epilogue: scale by ininv (UVf region) / outinv (UVt region), store fp16
    int r0 = tilebase + nodebase + (lane >> 2);
    int r1 = r0 + 8;
    float iin0 = 0.f, oin0 = 0.f, iin1 = 0.f, oin1 = 0.f;
    if (r0 < NN) { iin0 = g_ininv[r0]; oin0 = g_outinv[r0]; }
    if (r1 < NN) { iin1 = g_ininv[r1]; oin1 = g_outinv[r1]; }

    #pragma unroll
    for (int nt = 0; nt < 6; nt++) {
        int gc = 96 * chunk + colbase + 8 * nt + 2 * (lane & 3);
        if (r0 < NN) {
            if (gc < 64) {
                *(__half2*)(g_UVf + (size_t)r0 * 128 + gc) =
                    __floats2half2_rn(iin0 * acc[nt][0], iin0 * acc[nt][1]);
                *(__half2*)(g_UVt + (size_t)r0 * 128 + gc) =
                    __floats2half2_rn(oin0 * acc[nt][0], oin0 * acc[nt][1]);
            } else if (gc < 128) {
                *(__half2*)(g_UVf + (size_t)r0 * 128 + gc) =
                    __floats2half2_rn(iin0 * acc[nt][0], iin0 * acc[nt][1]);
            } else {
                *(__half2*)(g_UVt + (size_t)r0 * 128 + gc - 64) =
                    __floats2half2_rn(oin0 * acc[nt][0], oin0 * acc[nt][1]);
            }
        }
        if (r1 < NN) {
            if (gc < 64) {
                *(__half2*)(g_UVf + (size_t)r1 * 128 + gc) =
                    __floats2half2_rn(iin1 * acc[nt][2], iin1 * acc[nt][3]);
                *(__half2*)(g_UVt + (size_t)r1 * 128 + gc) =
                    __floats2half2_rn(oin1 * acc[nt][2], oin1 * acc[nt][3]);
            } else if (gc < 128) {
                *(__half2*)(g_UVf + (size_t)r1 * 128 + gc) =
                    __floats2half2_rn(iin1 * acc[nt][2], iin1 * acc[nt][3]);
            } else {
                *(__half2*)(g_UVt + (size_t)r1 * 128 + gc - 64) =
                    __floats2half2_rn(oin1 * acc[nt][2], oin1 * acc[nt][3]);
            }
        }
    }
}

// (A4) offsets: inline top-scan of the 98 block sums + in-block scan -> rs/cur
__global__ __launch_bounds__(1024) void k_offsets() {
    __shared__ int sf[1024], sr[1024];
    __shared__ int tf[128], tr[128];
    int t = threadIdx.x;

    if (t < 128) {
        tf[t] = (t < SCB) ? g_bsum_fwd[t] : 0;
        tr[t] = (t < SCB) ? g_bsum_rev[t] : 0;
    }
    __syncthreads();
    for (int off = 1; off < 128; off <<= 1) {
        int vf = 0, vr = 0, af = 0, ar = 0;
        if (t < 128) {
            vf = tf[t]; vr = tr[t];
            af = (t >= off) ? tf[t - off] : 0;
            ar = (t >= off) ? tr[t - off] : 0;
        }
        __syncthreads();
        if (t < 128) { tf[t] = vf + af; tr[t] = vr + ar; }
        __syncthreads();
    }
    int basef = (blockIdx.x == 0) ? 0 : tf[blockIdx.x - 1];
    int baser = (blockIdx.x == 0) ? 0 : tr[blockIdx.x - 1];

    int i = blockIdx.x * 1024 + t;
    int dout = (i < NN) ? g_degout[i] : 0;
    int din  = (i < NN) ? g_degin[i]  : 0;
    sf[t] = dout; sr[t] = din;
    __syncthreads();
    for (int off = 1; off < 1024; off <<= 1) {
        int vf = sf[t], vr = sr[t];
        int af = (t >= off) ? sf[t - off] : 0;
        int ar = (t >= off) ? sr[t - off] : 0;
        __syncthreads();
        sf[t] = vf + af; sr[t] = vr + ar;
        __syncthreads();
    }
    if (i < NN) {
        int of  = basef + sf[t] - dout;   // exclusive
        int orv = baser + sr[t] - din;
        g_rs_fwd[i] = of;  g_cur_fwd[i] = of;
        g_rs_rev[i] = orv; g_cur_rev[i] = orv;
    }
    if (i == NN - 1) { g_rs_fwd[NN] = NE; g_rs_rev[NN] = NE; }
}

// (A5) CSR placement: 2 edges per thread via int2 loads
__global__ void k_place(const int* __restrict__ ei) {
    int i = blockIdx.x * blockDim.x + threadIdx.x;
    int e = i * 2;
    if (e < NE) {
        int2 rows = *(const int2*)(ei + e);
        int2 cols = *(const int2*)(ei + NE + e);
        int p0 = atomicAdd(&g_cur_fwd[rows.x], 1);
        g_csr_fwd[p0] = cols.x;
        int q0 = atomicAdd(&g_cur_rev[cols.x], 1);
        g_csr_rev[q0] = rows.x;
        int p1 = atomicAdd(&g_cur_fwd[rows.y], 1);
        g_csr_fwd[p1] = cols.y;
        int q1 = atomicAdd(&g_cur_rev[cols.y], 1);
        g_csr_rev[q1] = rows.y;
    }
}

// (J) Pull-mode gather, weight-free inner loop:
//   out = bias + outinv[n]*Σ_{fwd} UVf'[col] + ininv[n]*Σ_{rev} UVt'[row]
__global__ __launch_bounds__(256) void k_gather(float* __restrict__ out) {
    int n    = (blockIdx.x * 256 + threadIdx.x) >> 5;
    int lane = threadIdx.x & 31;
    if (n >= NN) return;

    float4 accF = make_float4(0.f, 0.f, 0.f, 0.f);
    float4 accR = make_float4(0.f, 0.f, 0.f, 0.f);

    // forward: outgoing edges (row == n), sum UVf'[col]
    {
        int s = g_rs_fwd[n], e = g_rs_fwd[n + 1];
        for (int base = s; base < e; base += 32) {
            int idxv = (base + lane < e) ? __ldg(g_csr_fwd + base + lane) : 0;
            int m = min(32, e - base);
            for (int j = 0; j < m; j++) {
                int idx = __shfl_sync(0xffffffffu, idxv, j);
                uint2 pk = __ldg((const uint2*)(g_UVf + (size_t)idx * 128) + lane);
                float2 f0 = __half22float2(*(const __half2*)&pk.x);
                float2 f1 = __half22float2(*(const __half2*)&pk.y);
                accF.x += f0.x; accF.y += f0.y; accF.z += f1.x; accF.w += f1.y;
            }
        }
    }
    // reverse: incoming edges (col == n), sum UVt'[row]
    {
        int s = g_rs_rev[n], e = g_rs_rev[n + 1];
        for (int base = s; base < e; base += 32) {
            int idxv = (base + lane < e) ? __ldg(g_csr_rev + base + lane) : 0;
            int m = min(32, e - base);
            for (int j = 0; j < m; j++) {
                int idx = __shfl_sync(0xffffffffu, idxv, j);
                uint2 pk = __ldg((const uint2*)(g_UVt + (size_t)idx * 128) + lane);
                float2 f0 = __half22float2(*(const __half2*)&pk.x);
                float2 f1 = __half22float2(*(const __half2*)&pk.y);
                accR.x += f0.x; accR.y += f0.y; accR.z += f1.x; accR.w += f1.y;
            }
        }
    }

    float sF = g_outinv[n];
    float sR = g_ininv[n];
    float4 b = ((const float4*)g_bias)[lane];
    float4 res;
    res.x = b.x + sF * accF.x + sR * accR.x;
    res.y = b.y + sF * accF.y + sR * accR.y;
    res.z = b.z + sF * accF.z + sR * accR.z;
    res.w = b.w + sF * accF.w + sR * accR.w;

    if (lane < 16) {
        ((float4*)(out + (size_t)n * DF))[lane] = res;
    } else {
        ((float4*)(out + (size_t)NN * DF + (size_t)n * DF))[lane - 16] = res;
    }
}

// ---------------- launch ----------------
extern "C" void kernel_launch(void* const* d_in, const int* in_sizes, int n_in,
                              void* d_out, int out_size) {
    const float* xr = (const float*)d_in[0];
    const float* xi = (const float*)d_in[1];
    const int*   ei = (const int*)  d_in[2];
    const float* Wr = (const float*)d_in[3];
    const float* br = (const float*)d_in[4];
    const float* Wi = (const float*)d_in[5];
    const float* bi = (const float*)d_in[6];
    float* out = (float*)d_out;

    // Fresh stream/events per call, never destroyed (bounded: few calls/process).
    // Fallback: sequential on default stream (dependency-correct either way).
    cudaStream_t sB = 0;
    cudaEvent_t evF = 0, evI = 0, evJ = 0;
    bool forked = true;
    if (cudaStreamCreateWithFlags(&sB, cudaStreamNonBlocking) != cudaSuccess) { sB = 0; forked = false; }
    if (forked && cudaEventCreateWithFlags(&evF, cudaEventDisableTiming) != cudaSuccess) { forked = false; sB = 0; }
    if (forked && cudaEventCreateWithFlags(&evI, cudaEventDisableTiming) != cudaSuccess) { forked = false; sB = 0; }
    if (forked && cudaEventCreateWithFlags(&evJ, cudaEventDisableTiming) != cudaSuccess) { forked = false; sB = 0; }

    if (forked) { cudaEventRecord(evF, 0); cudaStreamWaitEvent(sB, evF, 0); }

    k_weights<<<96, 256, 0, sB>>>(Wr, br, Wi, bi);   // chain B start

    k_zero<<<(NN + 255) / 256, 256>>>();
    k_deg<<<(NE + 255) / 256, 256>>>(ei);
    k_bsum_inv<<<SCB, 1024>>>();                     // writes inv arrays

    if (forked) { cudaEventRecord(evI, 0); cudaStreamWaitEvent(sB, evI, 0); }
    k_transform<<<dim3(NTILE, 2), 256, 0, sB>>>(xr, xi);  // needs Wcat + inv
    if (forked) cudaEventRecord(evJ, sB);

    k_offsets<<<SCB, 1024>>>();                      // overlaps transform
    k_place<<<(NE / 2 + 255) / 256, 256>>>(ei);

    if (forked) cudaStreamWaitEvent(0, evJ, 0);
    k_gather<<<(NN * 32 + 255) / 256, 256>>>(out);
}

// round 13
// speedup vs baseline: 1.0870x; 1.0870x over previous
#include <cuda_runtime.h>
#include <cuda_fp16.h>
#include <math.h>

#define NN 100000
#define NE 1600000
#define DF 64
#define SCB 98                // scan blocks: ceil(NN/1024)
#define XTS 136               // padded smem row stride in halfs (X and W tiles)
#define NTILE 1563            // ceil(NN/64)

typedef unsigned long long ull;

// ---------------- device scratch (static: no allocation allowed) ----------------
__device__ __half g_UVf[NN * 128];  // node c: ininv[c]*{U, Vf}   (fp16, pre-scaled)
__device__ __half g_UVt[NN * 128];  // node r: outinv[r]*{U, Vt}  (fp16, pre-scaled)
__device__ __half g_Wcat[192 * 128];// fused weights: rows = out col, cols = [xr|xi]
__device__ float g_outinv[NN];
__device__ float g_ininv [NN];
__device__ int   g_degout[NN];
__device__ int   g_degin [NN];
__device__ int   g_rs_fwd[NN + 1];
__device__ int   g_rs_rev[NN + 1];
__device__ int   g_cur_fwd[NN];
__device__ int   g_cur_rev[NN];
__device__ int   g_csr_fwd[NE];
__device__ int   g_csr_rev[NE];
__device__ int   g_bsum_fwd[SCB];
__device__ int   g_bsum_rev[SCB];
__device__ float g_bias[128];       // [0:64) breal_eff, [64:128) bimag_eff

// ---------------- helpers ----------------
__device__ __forceinline__ unsigned smem_u32(const void* p) {
    unsigned a;
    asm("{ .reg .u64 t; cvta.to.shared.u64 t, %1; cvt.u32.u64 %0, t; }" : "=r"(a) : "l"(p));
    return a;
}

// ---------------- kernels ----------------
// (1) zero degree counters + build fused fp16 weight matrix Wcat + biases
__global__ void k_zero_weights(const float* __restrict__ Wr, const float* __restrict__ br,
                               const float* __restrict__ Wi, const float* __restrict__ bi) {
    int i = blockIdx.x * blockDim.x + threadIdx.x;
    if (i < NN) { g_degout[i] = 0; g_degin[i] = 0; }
    if (i < 192 * 128) {
        int gc = i >> 7, d2 = i & 127;
        float val = 0.0f;
        if (gc < 64) {
            int o = gc;
            if (d2 < 64) {
                int u = o * 64 + d2;
                val = 0.5f * (Wr[u] + 0.5f * Wr[4096 + u] + 0.25f * Wr[8192 + u]);
            } else {
                int u = o * 64 + (d2 - 64);
                val = -0.5f * (Wi[u] + 0.5f * Wi[4096 + u] + 0.25f * Wi[8192 + u]);
            }
        } else if (gc < 128) {
            int j = gc - 64;
            if (d2 < 64) {
                int u = j * 64 + d2;
                val = Wi[u] + 0.5f * Wi[4096 + u] + 0.25f * Wi[8192 + u];
            } else {
                int u = j * 64 + (d2 - 64);
                val = 0.5f * (Wr[u] + 0.5f * Wr[4096 + u] + 0.25f * Wr[8192 + u]);
            }
        } else {
            int j = gc - 128;
            if (d2 >= 64) {
                int u = j * 64 + (d2 - 64);
                val = 0.5f * (Wr[u] + 0.5f * Wr[4096 + u] + 0.25f * Wr[8192 + u]);
            }
        }
        g_Wcat[i] = __float2half_rn(val);
    }
    if (i < DF) {
        float bre = br[i] + 0.5f * br[64 + i] + 0.25f * br[128 + i];
        float bie = bi[i] + 0.5f * bi[64 + i] + 0.25f * bi[128 + i];
        g_bias[i]      = bre - bie;
        g_bias[64 + i] = bre + bie;
    }
}

// (2) degree counting, 2 edges per thread via int2
__global__ void k_deg(const int* __restrict__ ei) {
    int i = blockIdx.x * blockDim.x + threadIdx.x;
    int e = i * 2;
    if (e < NE) {
        int2 rows = *(const int2*)(ei + e);
        int2 cols = *(const int2*)(ei + NE + e);
        atomicAdd(&g_degout[rows.x], 1);
        atomicAdd(&g_degin [cols.x], 1);
        atomicAdd(&g_degout[rows.y], 1);
        atomicAdd(&g_degin [cols.y], 1);
    }
}

// (3) per-block degree sums + deg^-0.25 normalizers (fused)
__global__ __launch_bounds__(1024) void k_bsum_inv() {
    __shared__ int sf[1024], sr[1024];
    int t = threadIdx.x;
    int i = blockIdx.x * 1024 + t;
    int dout = 0, din = 0;
    if (i < NN) {
        dout = g_degout[i];
        din  = g_degin[i];
        g_outinv[i] = (dout > 0) ? rsqrtf(sqrtf((float)dout)) : 0.0f;
        g_ininv [i] = (din  > 0) ? rsqrtf(sqrtf((float)din )) : 0.0f;
    }
    sf[t] = dout; sr[t] = din;
    __syncthreads();
    for (int off = 512; off > 0; off >>= 1) {
        if (t < off) { sf[t] += sf[t + off]; sr[t] += sr[t + off]; }
        __syncthreads();
    }
    if (t == 0) {
        g_bsum_fwd[blockIdx.x] = sf[0];
        g_bsum_rev[blockIdx.x] = sr[0];
    }
}

// (4) HMMA transform with weight folding: outputs pre-scaled by ininv/outinv.
__global__ __launch_bounds__(256) void k_transform(const float* __restrict__ xr,
                                                   const float* __restrict__ xi) {
    __shared__ __align__(16) __half sX[64 * XTS];
    __shared__ __align__(16) __half sW[96 * XTS];

    int t    = threadIdx.x;
    int lane = t & 31;
    int w    = t >> 5;
    int tilebase = blockIdx.x * 64;
    int chunk    = blockIdx.y;            // 0 or 1

    #pragma unroll
    for (int it = 0; it < 8; it++) {
        int idx = t + it * 256;
        int nd = idx >> 5, k = idx & 31;
        int node = tilebase + nd;
        float4 v = make_float4(0.f, 0.f, 0.f, 0.f);
        if (node < NN)
            v = (k < 16) ? ((const float4*)xr)[(size_t)node * 16 + k]
                         : ((const float4*)xi)[(size_t)node * 16 + (k - 16)];
        __half2 h0 = __floats2half2_rn(v.x, v.y);
        __half2 h1 = __floats2half2_rn(v.z, v.w);
        *(uint2*)(sX + nd * XTS + k * 4) = make_uint2(*(unsigned*)&h0, *(unsigned*)&h1);
    }
    #pragma unroll
    for (int it = 0; it < 12; it++) {
        int idx = t + it * 256;
        int r = idx >> 5, c = idx & 31;
        uint2 v = ((const uint2*)g_Wcat)[((size_t)(96 * chunk + r) << 5) + c];
        *(uint2*)(sW + r * XTS + c * 4) = v;
    }
    __syncthreads();

    int ngrp = w & 3;
    int ns   = w >> 2;
    int nodebase = 16 * ngrp;
    int colbase  = 48 * ns;

    unsigned a_addr = smem_u32(sX) +
        (unsigned)(((nodebase + (lane & 15)) * XTS + ((lane >> 4) * 8)) * 2);
    unsigned b_addr = smem_u32(sW) +
        (unsigned)(((colbase + ((lane >> 4) & 1) * 8 + (lane & 7)) * XTS
                    + ((lane >> 3) & 1) * 8) * 2);

    float acc[6][4];
    #pragma unroll
    for (int nt = 0; nt < 6; nt++)
        #pragma unroll
        for (int q = 0; q < 4; q++) acc[nt][q] = 0.0f;

    #pragma unroll
    for (int kk = 0; kk < 8; kk++) {
        unsigned a0, a1, a2, a3;
        asm volatile("ldmatrix.sync.aligned.m8n8.x4.shared.b16 {%0,%1,%2,%3}, [%4];"
                     : "=r"(a0), "=r"(a1), "=r"(a2), "=r"(a3)
                     : "r"(a_addr + kk * 32));
        #pragma unroll
        for (int p = 0; p < 3; p++) {
            unsigned b0, b1, b2, b3;
            asm volatile("ldmatrix.sync.aligned.m8n8.x4.shared.b16 {%0,%1,%2,%3}, [%4];"
                         : "=r"(b0), "=r"(b1), "=r"(b2), "=r"(b3)
                         : "r"(b_addr + p * (16 * XTS * 2) + kk * 32));
            asm volatile("mma.sync.aligned.m16n8k16.row.col.f32.f16.f16.f32 "
                         "{%0,%1,%2,%3}, {%4,%5,%6,%7}, {%8,%9}, {%0,%1,%2,%3};"
                         : "+f"(acc[2*p][0]), "+f"(acc[2*p][1]),
                           "+f"(acc[2*p][2]), "+f"(acc[2*p][3])
                         : "r"(a0), "r"(a1), "r"(a2), "r"(a3), "r"(b0), "r"(b1));
            asm volatile("mma.sync.aligned.m16n8k16.row.col.f32.f16.f16.f32 "
                         "{%0,%1,%2,%3}, {%4,%5,%6,%7}, {%8,%9}, {%0,%1,%2,%3};"
                         : "+f"(acc[2*p+1][0]), "+f"(acc[2*p+1][1]),
                           "+f"(acc[2*p+1][2]), "+f"(acc[2*p+1][3])
                         : "r"(a0), "r"(a1), "r"(a2), "r"(a3), "r"(b2), "r"(b3));
        }
    }

    // epilogue: scale by ininv (UVf) / outinv (UVt), store fp16
    int r0 = tilebase + nodebase + (lane >> 2);
    int r1 = r0 + 8;
    float iin0 = 0.f, oin0 = 0.f, iin1 = 0.f, oin1 = 0.f;
    if (r0 < NN) { iin0 = g_ininv[r0]; oin0 = g_outinv[r0]; }
    if (r1 < NN) { iin1 = g_ininv[r1]; oin1 = g_outinv[r1]; }

    #pragma unroll
    for (int nt = 0; nt < 6; nt++) {
        int gc = 96 * chunk + colbase + 8 * nt + 2 * (lane & 3);
        if (r0 < NN) {
            if (gc < 64) {
                *(__half2*)(g_UVf + (size_t)r0 * 128 + gc) =
                    __floats2half2_rn(iin0 * acc[nt][0], iin0 * acc[nt][1]);
                *(__half2*)(g_UVt + (size_t)r0 * 128 + gc) =
                    __floats2half2_rn(oin0 * acc[nt][0], oin0 * acc[nt][1]);
            } else if (gc < 128) {
                *(__half2*)(g_UVf + (size_t)r0 * 128 + gc) =
                    __floats2half2_rn(iin0 * acc[nt][0], iin0 * acc[nt][1]);
            } else {
                *(__half2*)(g_UVt + (size_t)r0 * 128 + gc - 64) =
                    __floats2half2_rn(oin0 * acc[nt][0], oin0 * acc[nt][1]);
            }
        }
        if (r1 < NN) {
            if (gc < 64) {
                *(__half2*)(g_UVf + (size_t)r1 * 128 + gc) =
                    __floats2half2_rn(iin1 * acc[nt][2], iin1 * acc[nt][3]);
                *(__half2*)(g_UVt + (size_t)r1 * 128 + gc) =
                    __floats2half2_rn(oin1 * acc[nt][2], oin1 * acc[nt][3]);
            } else if (gc < 128) {
                *(__half2*)(g_UVf + (size_t)r1 * 128 + gc) =
                    __floats2half2_rn(iin1 * acc[nt][2], iin1 * acc[nt][3]);
            } else {
                *(__half2*)(g_UVt + (size_t)r1 * 128 + gc - 64) =
                    __floats2half2_rn(oin1 * acc[nt][2], oin1 * acc[nt][3]);
            }
        }
    }
}

// (5) offsets: inline top-scan of the 98 block sums + in-block scan -> rs/cur
__global__ __launch_bounds__(1024) void k_offsets() {
    __shared__ int sf[1024], sr[1024];
    __shared__ int tf[128], tr[128];
    int t = threadIdx.x;

    if (t < 128) {
        tf[t] = (t < SCB) ? g_bsum_fwd[t] : 0;
        tr[t] = (t < SCB) ? g_bsum_rev[t] : 0;
    }
    __syncthreads();
    for (int off = 1; off < 128; off <<= 1) {
        int vf = 0, vr = 0, af = 0, ar = 0;
        if (t < 128) {
            vf = tf[t]; vr = tr[t];
            af = (t >= off) ? tf[t - off] : 0;
            ar = (t >= off) ? tr[t - off] : 0;
        }
        __syncthreads();
        if (t < 128) { tf[t] = vf + af; tr[t] = vr + ar; }
        __syncthreads();
    }
    int basef = (blockIdx.x == 0) ? 0 : tf[blockIdx.x - 1];
    int baser = (blockIdx.x == 0) ? 0 : tr[blockIdx.x - 1];

    int i = blockIdx.x * 1024 + t;
    int dout = (i < NN) ? g_degout[i] : 0;
    int din  = (i < NN) ? g_degin[i]  : 0;
    sf[t] = dout; sr[t] = din;
    __syncthreads();
    for (int off = 1; off < 1024; off <<= 1) {
        int vf = sf[t], vr = sr[t];
        int af = (t >= off) ? sf[t - off] : 0;
        int ar = (t >= off) ? sr[t - off] : 0;
        __syncthreads();
        sf[t] = vf + af; sr[t] = vr + ar;
        __syncthreads();
    }
    if (i < NN) {
        int of  = basef + sf[t] - dout;   // exclusive
        int orv = baser + sr[t] - din;
        g_rs_fwd[i] = of;  g_cur_fwd[i] = of;
        g_rs_rev[i] = orv; g_cur_rev[i] = orv;
    }
    if (i == NN - 1) { g_rs_fwd[NN] = NE; g_rs_rev[NN] = NE; }
}

// (6) CSR placement: 2 edges per thread via int2 loads
__global__ void k_place(const int* __restrict__ ei) {
    int i = blockIdx.x * blockDim.x + threadIdx.x;
    int e = i * 2;
    if (e < NE) {
        int2 rows = *(const int2*)(ei + e);
        int2 cols = *(const int2*)(ei + NE + e);
        int p0 = atomicAdd(&g_cur_fwd[rows.x], 1);
        g_csr_fwd[p0] = cols.x;
        int q0 = atomicAdd(&g_cur_rev[cols.x], 1);
        g_csr_rev[q0] = rows.x;
        int p1 = atomicAdd(&g_cur_fwd[rows.y], 1);
        g_csr_fwd[p1] = cols.y;
        int q1 = atomicAdd(&g_cur_rev[cols.y], 1);
        g_csr_rev[q1] = rows.y;
    }
}

// (7) Pull-mode gather, weight-free inner loop:
//   out = bias + outinv[n]*Σ_{fwd} UVf'[col] + ininv[n]*Σ_{rev} UVt'[row]
__global__ __launch_bounds__(256) void k_gather(float* __restrict__ out) {
    int n    = (blockIdx.x * 256 + threadIdx.x) >> 5;
    int lane = threadIdx.x & 31;
    if (n >= NN) return;

    float4 accF = make_float4(0.f, 0.f, 0.f, 0.f);
    float4 accR = make_float4(0.f, 0.f, 0.f, 0.f);

    // forward: outgoing edges (row == n), sum UVf'[col]
    {
        int s = g_rs_fwd[n], e = g_rs_fwd[n + 1];
        for (int base = s; base < e; base += 32) {
            int idxv = (base + lane < e) ? __ldg(g_csr_fwd + base + lane) : 0;
            int m = min(32, e - base);
            for (int j = 0; j < m; j++) {
                int idx = __shfl_sync(0xffffffffu, idxv, j);
                uint2 pk = __ldg((const uint2*)(g_UVf + (size_t)idx * 128) + lane);
                float2 f0 = __half22float2(*(const __half2*)&pk.x);
                float2 f1 = __half22float2(*(const __half2*)&pk.y);
                accF.x += f0.x; accF.y += f0.y; accF.z += f1.x; accF.w += f1.y;
            }
        }
    }
    // reverse: incoming edges (col == n), sum UVt'[row]
    {
        int s = g_rs_rev[n], e = g_rs_rev[n + 1];
        for (int base = s; base < e; base += 32) {
            int idxv = (base + lane < e) ? __ldg(g_csr_rev + base + lane) : 0;
            int m = min(32, e - base);
            for (int j = 0; j < m; j++) {
                int idx = __shfl_sync(0xffffffffu, idxv, j);
                uint2 pk = __ldg((const uint2*)(g_UVt + (size_t)idx * 128) + lane);
                float2 f0 = __half22float2(*(const __half2*)&pk.x);
                float2 f1 = __half22float2(*(const __half2*)&pk.y);
                accR.x += f0.x; accR.y += f0.y; accR.z += f1.x; accR.w += f1.y;
            }
        }
    }

    float sF = g_outinv[n];
    float sR = g_ininv[n];
    float4 b = ((const float4*)g_bias)[lane];
    float4 res;
    res.x = b.x + sF * accF.x + sR * accR.x;
    res.y = b.y + sF * accF.y + sR * accR.y;
    res.z = b.z + sF * accF.z + sR * accR.z;
    res.w = b.w + sF * accF.w + sR * accR.w;

    if (lane < 16) {
        ((float4*)(out + (size_t)n * DF))[lane] = res;
    } else {
        ((float4*)(out + (size_t)NN * DF + (size_t)n * DF))[lane - 16] = res;
    }
}

// ---------------- launch: fully sequential, single stream ----------------
extern "C" void kernel_launch(void* const* d_in, const int* in_sizes, int n_in,
                              void* d_out, int out_size) {
    const float* xr = (const float*)d_in[0];
    const float* xi = (const float*)d_in[1];
    const int*   ei = (const int*)  d_in[2];
    const float* Wr = (const float*)d_in[3];
    const float* br = (const float*)d_in[4];
    const float* Wi = (const float*)d_in[5];
    const float* bi = (const float*)d_in[6];
    float* out = (float*)d_out;

    k_zero_weights<<<(NN + 255) / 256, 256>>>(Wr, br, Wi, bi);
    k_deg<<<(NE / 2 + 255) / 256, 256>>>(ei);
    k_bsum_inv<<<SCB, 1024>>>();
    k_transform<<<dim3(NTILE, 2), 256>>>(xr, xi);   // position 4: profiled launch
    k_offsets<<<SCB, 1024>>>();
    k_place<<<(NE / 2 + 255) / 256, 256>>>(ei);
    k_gather<<<(NN * 32 + 255) / 256, 256>>>(out);
}